// round 3
// baseline (speedup 1.0000x reference)
#include <cuda_runtime.h>

// Problem constants
#define B_   16
#define L_   4096
#define G_   256
#define R_   84
#define W_   169          // 2R+1
#define DMAX 12
#define VOCAB 25          // 2*DMAX+1

// Output section offsets (elements) — concatenation in reference return order
#define O_L2L_ATT 0LL
#define O_G2G_ATT 11075584LL
#define O_L2G_ATT 12124160LL
#define O_G2L_ATT 28901376LL
#define O_L2L_REL 45678592LL
#define O_G2G_REL 56754176LL
#define O_L2G_REL 57802752LL
#define O_G2L_REL 74579968LL

// Scratch (no cudaMalloc allowed)
static __device__ int g_seg[B_ * L_];    // suffix cumsum of long breakpoints
static __device__ int g_code[B_ * L_];   // pid | (long_token << 16)
static __device__ int g_gseg[B_ * G_];   // suffix cumsum of global breakpoints

__device__ __forceinline__ int rel_id(int r) {
    r = r < -DMAX ? -DMAX : (r > DMAX ? DMAX : r);
    return r >= 0 ? r : (DMAX - r);
}

// ---------------------------------------------------------------------------
// Kernel 1: per-batch suffix cumsums + packed code. 16 blocks x 1024 threads.
// ---------------------------------------------------------------------------
__global__ void __launch_bounds__(1024) scan_k(const int* __restrict__ bp,
                                               const int* __restrict__ pid,
                                               const int* __restrict__ gbp) {
    int b = blockIdx.x;
    int t = threadIdx.x;
    __shared__ int s[1024];

    // --- long sequence: 4096 elems, 4 per thread ---
    int4 v = ((const int4*)(bp + b * L_))[t];
    int total = v.x + v.y + v.z + v.w;
    s[t] = total;
    __syncthreads();
    // inclusive suffix scan over 1024 chunk totals (Hillis-Steele)
    for (int off = 1; off < 1024; off <<= 1) {
        int add = (t + off < 1024) ? s[t + off] : 0;
        __syncthreads();
        s[t] += add;
        __syncthreads();
    }
    int later = s[t] - total;               // sum of chunks strictly after t
    int e3 = v.w + later;
    int e2 = v.z + e3;
    int e1 = v.y + e2;
    int e0 = v.x + e1;
    ((int4*)(g_seg + b * L_))[t] = make_int4(e0, e1, e2, e3);

    int4 p = ((const int4*)(pid + b * L_))[t];
    int4 c;
    c.x = p.x | (((int)(e0 > 0)) << 16);
    c.y = p.y | (((int)(e1 > 0)) << 16);
    c.z = p.z | (((int)(e2 > 0)) << 16);
    c.w = p.w | (((int)(e3 > 0)) << 16);
    ((int4*)(g_code + b * L_))[t] = c;

    // --- global sequence: 256 elems ---
    __syncthreads();
    if (t < G_) s[t] = gbp[b * G_ + t];
    __syncthreads();
    for (int off = 1; off < G_; off <<= 1) {
        int add = (t < G_ && t + off < G_) ? s[t + off] : 0;
        __syncthreads();
        if (t < G_) s[t] += add;
        __syncthreads();
    }
    if (t < G_) g_gseg[b * G_ + t] = s[t];
}

// ---------------------------------------------------------------------------
// Kernel 2: l2l_att + l2l_rel  (B,L,169). float4 over flat index.
// ---------------------------------------------------------------------------
__global__ void __launch_bounds__(256) l2l_k(float* __restrict__ out) {
    const unsigned V = (unsigned)(B_ * L_ * W_ / 4);  // 2,768,896 vec4
    float4* att = (float4*)(out + O_L2L_ATT);
    float4* rel = (float4*)(out + O_L2L_REL);
    unsigned stride = gridDim.x * blockDim.x;
    for (unsigned vIdx = blockIdx.x * blockDim.x + threadIdx.x; vIdx < V; vIdx += stride) {
        unsigned base = vIdx * 4u;
        float a[4], r[4];
#pragma unroll
        for (int k = 0; k < 4; k++) {
            unsigned idx = base + k;
            int w   = (int)(idx % W_);
            int row = (int)(idx / W_);
            int i = row & (L_ - 1);
            int b = row >> 12;
            int si = __ldg(&g_seg[b * L_ + i]);
            int j = i + w - R_;
            int m = 0;
            if (j >= 0 && j < L_) m = (__ldg(&g_seg[b * L_ + j]) == si) ? 1 : 0;
            a[k] = (float)m;
            r[k] = (float)rel_id(w - R_);
        }
        att[vIdx] = make_float4(a[0], a[1], a[2], a[3]);
        rel[vIdx] = make_float4(r[0], r[1], r[2], r[3]);
    }
}

// ---------------------------------------------------------------------------
// Kernel 3: g2g_att + g2g_rel  (B,G,G).
// ---------------------------------------------------------------------------
__global__ void __launch_bounds__(256) g2g_k(float* __restrict__ out) {
    const unsigned V = (unsigned)(B_ * G_ * G_ / 4);  // 262,144 vec4
    float4* att = (float4*)(out + O_G2G_ATT);
    float4* rel = (float4*)(out + O_G2G_REL);
    unsigned stride = gridDim.x * blockDim.x;
    for (unsigned vIdx = blockIdx.x * blockDim.x + threadIdx.x; vIdx < V; vIdx += stride) {
        int h4  = (int)(vIdx & 63u) * 4;
        int row = (int)(vIdx >> 6);
        int g = row & (G_ - 1);
        int b = row >> 8;
        int sg = __ldg(&g_gseg[b * G_ + g]);
        int tg = sg > 0;
        float a[4], r[4];
#pragma unroll
        for (int k = 0; k < 4; k++) {
            int h  = h4 + k;
            int sh = __ldg(&g_gseg[b * G_ + h]);
            a[k] = (tg == (sh > 0)) ? 1.0f : 0.0f;
            r[k] = (float)((sg == sh) ? rel_id(h - g) : (VOCAB + 2));
        }
        att[vIdx] = make_float4(a[0], a[1], a[2], a[3]);
        rel[vIdx] = make_float4(r[0], r[1], r[2], r[3]);
    }
}

// ---------------------------------------------------------------------------
// Kernel 4: l2g_att + l2g_rel  (B,L,G). Inner dim g.
// ---------------------------------------------------------------------------
__global__ void __launch_bounds__(256) l2g_k(float* __restrict__ out) {
    const unsigned V = (unsigned)(B_ * L_ * G_ / 4);  // 4,194,304 vec4
    float4* att = (float4*)(out + O_L2G_ATT);
    float4* rel = (float4*)(out + O_L2G_REL);
    unsigned stride = gridDim.x * blockDim.x;
    for (unsigned vIdx = blockIdx.x * blockDim.x + threadIdx.x; vIdx < V; vIdx += stride) {
        int g4  = (int)(vIdx & 63u) * 4;
        int row = (int)(vIdx >> 6);
        int i = row & (L_ - 1);
        int b = row >> 12;
        int code = __ldg(&g_code[b * L_ + i]);
        int pid = code & 0xFFFF;
        int lt  = code >> 16;
        int gtp = __ldg(&g_gseg[b * G_ + pid]) > 0;
        float a[4], r[4];
#pragma unroll
        for (int k = 0; k < 4; k++) {
            int g  = g4 + k;
            int eq = (g == pid) ? 1 : 0;
            a[k] = (eq && (lt == gtp)) ? 1.0f : 0.0f;
            r[k] = (float)(VOCAB + eq);
        }
        att[vIdx] = make_float4(a[0], a[1], a[2], a[3]);
        rel[vIdx] = make_float4(r[0], r[1], r[2], r[3]);
    }
}

// ---------------------------------------------------------------------------
// Kernel 5: g2l_att + g2l_rel  (B,G,L). Inner dim i.
// ---------------------------------------------------------------------------
__global__ void __launch_bounds__(256) g2l_k(float* __restrict__ out) {
    const unsigned V = (unsigned)(B_ * G_ * L_ / 4);  // 4,194,304 vec4
    float4* att = (float4*)(out + O_G2L_ATT);
    float4* rel = (float4*)(out + O_G2L_REL);
    unsigned stride = gridDim.x * blockDim.x;
    for (unsigned vIdx = blockIdx.x * blockDim.x + threadIdx.x; vIdx < V; vIdx += stride) {
        unsigned i4v = vIdx & 1023u;         // vec4 index within row
        int row = (int)(vIdx >> 10);
        int g = row & (G_ - 1);
        int b = row >> 8;
        int gt_g = __ldg(&g_gseg[b * G_ + g]) > 0;
        int4 c = ((const int4*)g_code)[b * (L_ / 4) + i4v];
        int cs[4] = {c.x, c.y, c.z, c.w};
        float a[4], r[4];
#pragma unroll
        for (int k = 0; k < 4; k++) {
            int pid = cs[k] & 0xFFFF;
            int lt  = cs[k] >> 16;
            int hard = (g == pid || g == 0) ? 1 : 0;
            a[k] = ((lt == gt_g) && hard) ? 1.0f : 0.0f;
            r[k] = (float)(VOCAB + ((pid == g) ? 1 : 0));
        }
        att[vIdx] = make_float4(a[0], a[1], a[2], a[3]);
        rel[vIdx] = make_float4(r[0], r[1], r[2], r[3]);
    }
}

// ---------------------------------------------------------------------------
extern "C" void kernel_launch(void* const* d_in, const int* in_sizes, int n_in,
                              void* d_out, int out_size) {
    // Robust input binding by element count:
    //  - the (B*G)=4096-element input is global_paragraph_breakpoints
    //  - the two (B*L)=65536-element inputs are long_paragraph_breakpoints then
    //    long_paragraph_ids (true for both insertion and alphabetical ordering)
    const int* bp  = nullptr;
    const int* pid = nullptr;
    const int* gbp = nullptr;
    for (int i = 0; i < n_in; i++) {
        if (in_sizes[i] == B_ * G_) {
            gbp = (const int*)d_in[i];
        } else {
            if (!bp) bp = (const int*)d_in[i];
            else     pid = (const int*)d_in[i];
        }
    }
    float* out = (float*)d_out;

    scan_k<<<B_, 1024>>>(bp, pid, gbp);

    l2l_k<<<(B_ * L_ * W_ / 4 + 255) / 256, 256>>>(out);
    g2g_k<<<(B_ * G_ * G_ / 4 + 255) / 256, 256>>>(out);
    l2g_k<<<(B_ * L_ * G_ / 4 + 255) / 256, 256>>>(out);
    g2l_k<<<(B_ * G_ * L_ / 4 + 255) / 256, 256>>>(out);
}